// round 7
// baseline (speedup 1.0000x reference)
#include <cuda_runtime.h>
#include <cuda_bf16.h>

// ---------------------------------------------------------------------------
// out[m] = sum_n I_n * exp(-0.5 * (x_m)^T A_n x_m - 2 b_n.x_m + c_n)
// Folded: t = K*(x^T A x - 2 b.x + c) + log2(I),  K = -0.5*log2(e)
//         out[m] = sum_n exp2(t)
// 10 coefficients per gaussian, pre-splatted as f32x2 pairs (80 B/gaussian) so
// the inner loop feeds fma.rn.f32x2 straight from LDS.128, no splat MOVs.
//
// R3: persistent flat-tile scheduler (one resident wave, <=4% tail imbalance)
//     + double-buffered cp.async staging of 64-gaussian chunks.
// ---------------------------------------------------------------------------

#define NG_MAX 8192
__device__ __align__(16) float g_coef[NG_MAX * 20];

#define GCHUNK 64            // gaussians per tile (5 KB smem per buffer)
#define PTS_PER_TILE 1024    // 256 threads * 4 points
#define CTAS_PER_SM 4

// ---- f32x2 packed helpers --------------------------------------------------
__device__ __forceinline__ unsigned long long fma2(unsigned long long a,
                                                   unsigned long long b,
                                                   unsigned long long c) {
    unsigned long long d;
    asm("fma.rn.f32x2 %0, %1, %2, %3;" : "=l"(d) : "l"(a), "l"(b), "l"(c));
    return d;
}
__device__ __forceinline__ unsigned long long add2(unsigned long long a,
                                                   unsigned long long b) {
    unsigned long long d;
    asm("add.rn.f32x2 %0, %1, %2;" : "=l"(d) : "l"(a), "l"(b));
    return d;
}
__device__ __forceinline__ unsigned long long mul2(unsigned long long a,
                                                   unsigned long long b) {
    unsigned long long d;
    asm("mul.rn.f32x2 %0, %1, %2;" : "=l"(d) : "l"(a), "l"(b));
    return d;
}
__device__ __forceinline__ unsigned long long pk2(float lo, float hi) {
    unsigned long long r;
    asm("mov.b64 %0, {%1, %2};" : "=l"(r) : "f"(lo), "f"(hi));
    return r;
}
__device__ __forceinline__ void upk2(unsigned long long v, float& lo, float& hi) {
    asm("mov.b64 {%0, %1}, %2;" : "=f"(lo), "=f"(hi) : "l"(v));
}
__device__ __forceinline__ float ex2(float x) {
    float y;
    asm("ex2.approx.ftz.f32 %0, %1;" : "=f"(y) : "f"(x));
    return y;
}
__device__ __forceinline__ unsigned int smem_u32(const void* p) {
    unsigned int a;
    asm("{ .reg .u64 t; cvta.to.shared.u64 t, %1; cvt.u32.u64 %0, t; }"
        : "=r"(a) : "l"(p));
    return a;
}
__device__ __forceinline__ void cp_async16(unsigned int dst, const void* src) {
    asm volatile("cp.async.cg.shared.global [%0], [%1], 16;"
                 :: "r"(dst), "l"(src));
}
__device__ __forceinline__ void cp_commit() {
    asm volatile("cp.async.commit_group;");
}
__device__ __forceinline__ void cp_wait1() {
    asm volatile("cp.async.wait_group 1;");
}
__device__ __forceinline__ void cp_wait0() {
    asm volatile("cp.async.wait_group 0;");
}

// ---------------------------------------------------------------------------
// Prep: coefficients; pads [n, n_pad) with cf = -inf (exp2 -> 0).
// ---------------------------------------------------------------------------
__global__ void prep_kernel(const float* __restrict__ positions,
                            const float* __restrict__ scales,
                            const float* __restrict__ rotations,
                            const float* __restrict__ intensities,
                            int n, int n_pad) {
    int g = blockIdx.x * blockDim.x + threadIdx.x;
    if (g >= n_pad || g >= NG_MAX) return;

    float v[10];
    if (g >= n) {
#pragma unroll
        for (int k = 0; k < 9; k++) v[k] = 0.0f;
        v[9] = -__int_as_float(0x7f800000);  // -inf
    } else {
        float qw = rotations[4 * g + 0];
        float qx = rotations[4 * g + 1];
        float qy = rotations[4 * g + 2];
        float qz = rotations[4 * g + 3];
        float nrm = sqrtf(qw * qw + qx * qx + qy * qy + qz * qz);
        float inv = 1.0f / (nrm + 1e-8f);
        qw *= inv; qx *= inv; qy *= inv; qz *= inv;

        float r00 = 1.0f - 2.0f * (qy * qy + qz * qz);
        float r01 = 2.0f * (qx * qy - qz * qw);
        float r02 = 2.0f * (qx * qz + qy * qw);
        float r10 = 2.0f * (qx * qy + qz * qw);
        float r11 = 1.0f - 2.0f * (qx * qx + qz * qz);
        float r12 = 2.0f * (qy * qz - qx * qw);
        float r20 = 2.0f * (qx * qz - qy * qw);
        float r21 = 2.0f * (qy * qz + qx * qw);
        float r22 = 1.0f - 2.0f * (qx * qx + qy * qy);

        float s0 = fabsf(scales[3 * g + 0]) + 1e-6f;
        float s1 = fabsf(scales[3 * g + 1]) + 1e-6f;
        float s2 = fabsf(scales[3 * g + 2]) + 1e-6f;
        float i0 = 1.0f / (s0 * s0);
        float i1 = 1.0f / (s1 * s1);
        float i2 = 1.0f / (s2 * s2);

        float a00 = r00 * r00 * i0 + r01 * r01 * i1 + r02 * r02 * i2;
        float a01 = r00 * r10 * i0 + r01 * r11 * i1 + r02 * r12 * i2;
        float a02 = r00 * r20 * i0 + r01 * r21 * i1 + r02 * r22 * i2;
        float a11 = r10 * r10 * i0 + r11 * r11 * i1 + r12 * r12 * i2;
        float a12 = r10 * r20 * i0 + r11 * r21 * i1 + r12 * r22 * i2;
        float a22 = r20 * r20 * i0 + r21 * r21 * i1 + r22 * r22 * i2;

        float px = positions[3 * g + 0];
        float py = positions[3 * g + 1];
        float pz = positions[3 * g + 2];
        float bx = a00 * px + a01 * py + a02 * pz;
        float by = a01 * px + a11 * py + a12 * pz;
        float bz = a02 * px + a12 * py + a22 * pz;
        float c  = bx * px + by * py + bz * pz;

        const float K = -0.72134752044448169f;  // -0.5 * log2(e)
        v[0] = K * a00;
        v[1] = K * a11;
        v[2] = K * a22;
        v[3] = 2.0f * K * a01;
        v[4] = 2.0f * K * a02;
        v[5] = 2.0f * K * a12;
        v[6] = -2.0f * K * bx;
        v[7] = -2.0f * K * by;
        v[8] = -2.0f * K * bz;
        v[9] = K * c + log2f(intensities[g]);
    }

#pragma unroll
    for (int k = 0; k < 10; k++) {
        g_coef[g * 20 + 2 * k + 0] = v[k];
        g_coef[g * 20 + 2 * k + 1] = v[k];
    }
}

// ---------------------------------------------------------------------------
// Persistent main kernel. Tile t: pb = t >> lg(gc_tiles)... flat index with
// gc-major-within-pb ordering so accumulators persist across gaussian chunks.
// ---------------------------------------------------------------------------
__global__ void __launch_bounds__(256, CTAS_PER_SM)
gauss_kernel(const float* __restrict__ pts, float* __restrict__ out,
             int M, int gc_tiles, int pb_tiles, int n_ctas) {
    __shared__ __align__(16) float sm[2][GCHUNK * 20];

    const int tid = threadIdx.x;
    const int cta = blockIdx.x;
    const int tiles = gc_tiles * pb_tiles;

    const int t0 = (int)(((long long)cta * tiles) / n_ctas);
    const int t1 = (int)(((long long)(cta + 1) * tiles) / n_ctas);
    if (t0 >= t1) return;

    const unsigned int sbase0 = smem_u32(&sm[0][0]);
    const unsigned int sbase1 = smem_u32(&sm[1][0]);

    // stage helper: tile's gaussian chunk gc -> buffer
    auto stage = [&](int t, unsigned int sbase) {
        int gc = t % gc_tiles;
        const char* src = (const char*)g_coef + (size_t)gc * GCHUNK * 80;
#pragma unroll
        for (int i = tid; i < GCHUNK * 5; i += 256) {
            cp_async16(sbase + i * 16, src + i * 16);
        }
        cp_commit();
    };

    stage(t0, sbase0);

    unsigned long long xA = 0, xB = 0, yA = 0, yB = 0, zA = 0, zB = 0;
    unsigned long long xxA = 0, xxB = 0, yyA = 0, yyB = 0, zzA = 0, zzB = 0;
    unsigned long long xyA = 0, xyB = 0, xzA = 0, xzB = 0, yzA = 0, yzB = 0;
    unsigned long long accA = 0, accB = 0;
    int cur_pb = -1;
    int p0 = 0;

    for (int t = t0; t < t1; ++t) {
        const int buf = (t - t0) & 1;
        const unsigned int sb = buf ? sbase1 : sbase0;

        if (t + 1 < t1) {
            stage(t + 1, buf ? sbase0 : sbase1);
            cp_wait1();
        } else {
            cp_wait0();
        }
        __syncthreads();

        const int pb = t / gc_tiles;
        if (pb != cur_pb) {
            // flush previous accumulators
            if (cur_pb >= 0) {
                float a0, a1, a2, a3;
                upk2(accA, a0, a1);
                upk2(accB, a2, a3);
                if (p0 < M)        atomicAdd(out + p0, a0);
                if (p0 + 256 < M)  atomicAdd(out + p0 + 256, a1);
                if (p0 + 512 < M)  atomicAdd(out + p0 + 512, a2);
                if (p0 + 768 < M)  atomicAdd(out + p0 + 768, a3);
            }
            cur_pb = pb;
            p0 = pb * PTS_PER_TILE + tid;
            float x[4], y[4], z[4];
#pragma unroll
            for (int j = 0; j < 4; j++) {
                int p = p0 + j * 256;
                bool ok = (p < M);
                x[j] = ok ? pts[3 * p + 0] : 0.0f;
                y[j] = ok ? pts[3 * p + 1] : 0.0f;
                z[j] = ok ? pts[3 * p + 2] : 0.0f;
            }
            xA = pk2(x[0], x[1]); xB = pk2(x[2], x[3]);
            yA = pk2(y[0], y[1]); yB = pk2(y[2], y[3]);
            zA = pk2(z[0], z[1]); zB = pk2(z[2], z[3]);
            xxA = mul2(xA, xA); xxB = mul2(xB, xB);
            yyA = mul2(yA, yA); yyB = mul2(yB, yB);
            zzA = mul2(zA, zA); zzB = mul2(zB, zB);
            xyA = mul2(xA, yA); xyB = mul2(xB, yB);
            xzA = mul2(xA, zA); xzB = mul2(xB, zB);
            yzA = mul2(yA, zA); yzB = mul2(yB, zB);
            accA = 0ull; accB = 0ull;
        }

        const ulonglong2* recs =
            (const ulonglong2*)(buf ? &sm[1][0] : &sm[0][0]);
#pragma unroll 2
        for (int g = 0; g < GCHUNK; ++g) {
            ulonglong2 q0 = recs[g * 5 + 0];  // Ka00 | Ka11
            ulonglong2 q1 = recs[g * 5 + 1];  // Ka22 | 2Ka01
            ulonglong2 q2 = recs[g * 5 + 2];  // 2Ka02 | 2Ka12
            ulonglong2 q3 = recs[g * 5 + 3];  // bx | by
            ulonglong2 q4 = recs[g * 5 + 4];  // bz | cf

            unsigned long long tA = fma2(q0.x, xxA, q4.y);
            unsigned long long tB = fma2(q0.x, xxB, q4.y);
            tA = fma2(q0.y, yyA, tA);  tB = fma2(q0.y, yyB, tB);
            tA = fma2(q1.x, zzA, tA);  tB = fma2(q1.x, zzB, tB);
            tA = fma2(q1.y, xyA, tA);  tB = fma2(q1.y, xyB, tB);
            tA = fma2(q2.x, xzA, tA);  tB = fma2(q2.x, xzB, tB);
            tA = fma2(q2.y, yzA, tA);  tB = fma2(q2.y, yzB, tB);
            tA = fma2(q3.x, xA,  tA);  tB = fma2(q3.x, xB,  tB);
            tA = fma2(q3.y, yA,  tA);  tB = fma2(q3.y, yB,  tB);
            tA = fma2(q4.x, zA,  tA);  tB = fma2(q4.x, zB,  tB);

            float f0, f1, f2, f3;
            upk2(tA, f0, f1);
            upk2(tB, f2, f3);
            float e0 = ex2(f0), e1 = ex2(f1), e2 = ex2(f2), e3 = ex2(f3);
            accA = add2(accA, pk2(e0, e1));
            accB = add2(accB, pk2(e2, e3));
        }
        __syncthreads();
    }

    // final flush
    if (cur_pb >= 0) {
        float a0, a1, a2, a3;
        upk2(accA, a0, a1);
        upk2(accB, a2, a3);
        if (p0 < M)        atomicAdd(out + p0, a0);
        if (p0 + 256 < M)  atomicAdd(out + p0 + 256, a1);
        if (p0 + 512 < M)  atomicAdd(out + p0 + 512, a2);
        if (p0 + 768 < M)  atomicAdd(out + p0 + 768, a3);
    }
}

// ---------------------------------------------------------------------------
extern "C" void kernel_launch(void* const* d_in, const int* in_sizes, int n_in,
                              void* d_out, int out_size) {
    const float* sample_points = (const float*)d_in[0];
    const float* positions     = (const float*)d_in[1];
    const float* scales        = (const float*)d_in[2];
    const float* rotations     = (const float*)d_in[3];
    const float* intensities   = (const float*)d_in[4];
    float* out = (float*)d_out;

    int M = in_sizes[0] / 3;
    int n = in_sizes[4];
    int n_pad = ((n + GCHUNK - 1) / GCHUNK) * GCHUNK;
    if (n_pad > NG_MAX) n_pad = NG_MAX;

    cudaMemsetAsync(out, 0, (size_t)out_size * sizeof(float));

    prep_kernel<<<(n_pad + 255) / 256, 256>>>(positions, scales, rotations,
                                              intensities, n, n_pad);

    int sms = 148;
    cudaDeviceGetAttribute(&sms, cudaDevAttrMultiProcessorCount, 0);
    int n_ctas = sms * CTAS_PER_SM;

    int pb_tiles = (M + PTS_PER_TILE - 1) / PTS_PER_TILE;   // 64
    int gc_tiles = n_pad / GCHUNK;                           // 64
    int tiles = pb_tiles * gc_tiles;
    if (n_ctas > tiles) n_ctas = tiles;

    gauss_kernel<<<n_ctas, 256>>>(sample_points, out, M, gc_tiles, pb_tiles,
                                  n_ctas);
}

// round 8
// speedup vs baseline: 1.1241x; 1.1241x over previous
#include <cuda_runtime.h>
#include <cuda_bf16.h>

// ---------------------------------------------------------------------------
// out[m] = sum_n I_n * exp(-0.5 * (x_m)^T A_n x_m - 2 b_n.x_m + c_n)
// Folded: t = K*(x^T A x - 2 b.x + c) + log2(I),  K = -0.5*log2(e)
//         out[m] = sum_n exp2(t)
// 10 coefficients per gaussian, pre-splatted as f32x2 pairs (80 B/gaussian).
//
// R8: 8 points/thread -> 4 independent f32x2 FMA chains per record (ILP x2),
//     2 CTAs/SM reg budget (128 regs, no spill of the 36 b64 point products),
//     persistent flat-tile scheduler, double-buffered cp.async staging.
// ---------------------------------------------------------------------------

#define NG_MAX 8192
__device__ __align__(16) float g_coef[NG_MAX * 20];

#define GCHUNK 64            // gaussians per tile (5 KB per smem buffer)
#define PTS_PER_TILE 2048    // 256 threads * 8 points
#define CTAS_PER_SM 2

// ---- f32x2 packed helpers --------------------------------------------------
__device__ __forceinline__ unsigned long long fma2(unsigned long long a,
                                                   unsigned long long b,
                                                   unsigned long long c) {
    unsigned long long d;
    asm("fma.rn.f32x2 %0, %1, %2, %3;" : "=l"(d) : "l"(a), "l"(b), "l"(c));
    return d;
}
__device__ __forceinline__ unsigned long long add2(unsigned long long a,
                                                   unsigned long long b) {
    unsigned long long d;
    asm("add.rn.f32x2 %0, %1, %2;" : "=l"(d) : "l"(a), "l"(b));
    return d;
}
__device__ __forceinline__ unsigned long long mul2(unsigned long long a,
                                                   unsigned long long b) {
    unsigned long long d;
    asm("mul.rn.f32x2 %0, %1, %2;" : "=l"(d) : "l"(a), "l"(b));
    return d;
}
__device__ __forceinline__ unsigned long long pk2(float lo, float hi) {
    unsigned long long r;
    asm("mov.b64 %0, {%1, %2};" : "=l"(r) : "f"(lo), "f"(hi));
    return r;
}
__device__ __forceinline__ void upk2(unsigned long long v, float& lo, float& hi) {
    asm("mov.b64 {%0, %1}, %2;" : "=f"(lo), "=f"(hi) : "l"(v));
}
__device__ __forceinline__ float ex2(float x) {
    float y;
    asm("ex2.approx.ftz.f32 %0, %1;" : "=f"(y) : "f"(x));
    return y;
}
__device__ __forceinline__ unsigned int smem_u32(const void* p) {
    unsigned int a;
    asm("{ .reg .u64 t; cvta.to.shared.u64 t, %1; cvt.u32.u64 %0, t; }"
        : "=r"(a) : "l"(p));
    return a;
}
__device__ __forceinline__ void cp_async16(unsigned int dst, const void* src) {
    asm volatile("cp.async.cg.shared.global [%0], [%1], 16;"
                 :: "r"(dst), "l"(src));
}
__device__ __forceinline__ void cp_commit() {
    asm volatile("cp.async.commit_group;");
}
__device__ __forceinline__ void cp_wait1() {
    asm volatile("cp.async.wait_group 1;");
}
__device__ __forceinline__ void cp_wait0() {
    asm volatile("cp.async.wait_group 0;");
}

// ---------------------------------------------------------------------------
// Prep: coefficients; pads [n, n_pad) with cf = -inf (exp2 -> 0).
// ---------------------------------------------------------------------------
__global__ void prep_kernel(const float* __restrict__ positions,
                            const float* __restrict__ scales,
                            const float* __restrict__ rotations,
                            const float* __restrict__ intensities,
                            int n, int n_pad) {
    int g = blockIdx.x * blockDim.x + threadIdx.x;
    if (g >= n_pad || g >= NG_MAX) return;

    float v[10];
    if (g >= n) {
#pragma unroll
        for (int k = 0; k < 9; k++) v[k] = 0.0f;
        v[9] = -__int_as_float(0x7f800000);  // -inf
    } else {
        float qw = rotations[4 * g + 0];
        float qx = rotations[4 * g + 1];
        float qy = rotations[4 * g + 2];
        float qz = rotations[4 * g + 3];
        float nrm = sqrtf(qw * qw + qx * qx + qy * qy + qz * qz);
        float inv = 1.0f / (nrm + 1e-8f);
        qw *= inv; qx *= inv; qy *= inv; qz *= inv;

        float r00 = 1.0f - 2.0f * (qy * qy + qz * qz);
        float r01 = 2.0f * (qx * qy - qz * qw);
        float r02 = 2.0f * (qx * qz + qy * qw);
        float r10 = 2.0f * (qx * qy + qz * qw);
        float r11 = 1.0f - 2.0f * (qx * qx + qz * qz);
        float r12 = 2.0f * (qy * qz - qx * qw);
        float r20 = 2.0f * (qx * qz - qy * qw);
        float r21 = 2.0f * (qy * qz + qx * qw);
        float r22 = 1.0f - 2.0f * (qx * qx + qy * qy);

        float s0 = fabsf(scales[3 * g + 0]) + 1e-6f;
        float s1 = fabsf(scales[3 * g + 1]) + 1e-6f;
        float s2 = fabsf(scales[3 * g + 2]) + 1e-6f;
        float i0 = 1.0f / (s0 * s0);
        float i1 = 1.0f / (s1 * s1);
        float i2 = 1.0f / (s2 * s2);

        float a00 = r00 * r00 * i0 + r01 * r01 * i1 + r02 * r02 * i2;
        float a01 = r00 * r10 * i0 + r01 * r11 * i1 + r02 * r12 * i2;
        float a02 = r00 * r20 * i0 + r01 * r21 * i1 + r02 * r22 * i2;
        float a11 = r10 * r10 * i0 + r11 * r11 * i1 + r12 * r12 * i2;
        float a12 = r10 * r20 * i0 + r11 * r21 * i1 + r12 * r22 * i2;
        float a22 = r20 * r20 * i0 + r21 * r21 * i1 + r22 * r22 * i2;

        float px = positions[3 * g + 0];
        float py = positions[3 * g + 1];
        float pz = positions[3 * g + 2];
        float bx = a00 * px + a01 * py + a02 * pz;
        float by = a01 * px + a11 * py + a12 * pz;
        float bz = a02 * px + a12 * py + a22 * pz;
        float c  = bx * px + by * py + bz * pz;

        const float K = -0.72134752044448169f;  // -0.5 * log2(e)
        v[0] = K * a00;
        v[1] = K * a11;
        v[2] = K * a22;
        v[3] = 2.0f * K * a01;
        v[4] = 2.0f * K * a02;
        v[5] = 2.0f * K * a12;
        v[6] = -2.0f * K * bx;
        v[7] = -2.0f * K * by;
        v[8] = -2.0f * K * bz;
        v[9] = K * c + log2f(intensities[g]);
    }

#pragma unroll
    for (int k = 0; k < 10; k++) {
        g_coef[g * 20 + 2 * k + 0] = v[k];
        g_coef[g * 20 + 2 * k + 1] = v[k];
    }
}

// ---------------------------------------------------------------------------
// Persistent main kernel; 8 points per thread as 4 f32x2 groups.
// ---------------------------------------------------------------------------
__global__ void __launch_bounds__(256, CTAS_PER_SM)
gauss_kernel(const float* __restrict__ pts, float* __restrict__ out,
             int M, int gc_tiles, int pb_tiles, int n_ctas) {
    __shared__ __align__(16) float sm[2][GCHUNK * 20];

    const int tid = threadIdx.x;
    const int cta = blockIdx.x;
    const int tiles = gc_tiles * pb_tiles;

    const int t0 = (int)(((long long)cta * tiles) / n_ctas);
    const int t1 = (int)(((long long)(cta + 1) * tiles) / n_ctas);
    if (t0 >= t1) return;

    const unsigned int sbase0 = smem_u32(&sm[0][0]);
    const unsigned int sbase1 = smem_u32(&sm[1][0]);

    auto stage = [&](int t, unsigned int sbase) {
        int gc = t % gc_tiles;
        const char* src = (const char*)g_coef + (size_t)gc * GCHUNK * 80;
#pragma unroll
        for (int i = tid; i < GCHUNK * 5; i += 256) {
            cp_async16(sbase + i * 16, src + i * 16);
        }
        cp_commit();
    };

    stage(t0, sbase0);

    // 4 f32x2 groups (8 points): coords, products, accumulators
    unsigned long long X[4], Y[4], Z[4];
    unsigned long long XX[4], YY[4], ZZ[4], XY[4], XZ[4], YZ[4];
    unsigned long long ACC[4];
    int cur_pb = -1;
    int p0 = 0;

    for (int t = t0; t < t1; ++t) {
        const int buf = (t - t0) & 1;

        if (t + 1 < t1) {
            stage(t + 1, buf ? sbase0 : sbase1);
            cp_wait1();
        } else {
            cp_wait0();
        }
        __syncthreads();

        const int pb = t / gc_tiles;
        if (pb != cur_pb) {
            if (cur_pb >= 0) {
#pragma unroll
                for (int j = 0; j < 4; j++) {
                    float a0, a1;
                    upk2(ACC[j], a0, a1);
                    int p = p0 + j * 512;
                    if (p < M)       atomicAdd(out + p, a0);
                    if (p + 256 < M) atomicAdd(out + p + 256, a1);
                }
            }
            cur_pb = pb;
            p0 = pb * PTS_PER_TILE + tid;
#pragma unroll
            for (int j = 0; j < 4; j++) {
                int pa = p0 + j * 512;
                int pb2 = pa + 256;
                bool oka = (pa < M), okb = (pb2 < M);
                float xa = oka ? pts[3 * pa + 0] : 0.0f;
                float ya = oka ? pts[3 * pa + 1] : 0.0f;
                float za = oka ? pts[3 * pa + 2] : 0.0f;
                float xb = okb ? pts[3 * pb2 + 0] : 0.0f;
                float yb = okb ? pts[3 * pb2 + 1] : 0.0f;
                float zb = okb ? pts[3 * pb2 + 2] : 0.0f;
                X[j] = pk2(xa, xb);
                Y[j] = pk2(ya, yb);
                Z[j] = pk2(za, zb);
                XX[j] = mul2(X[j], X[j]);
                YY[j] = mul2(Y[j], Y[j]);
                ZZ[j] = mul2(Z[j], Z[j]);
                XY[j] = mul2(X[j], Y[j]);
                XZ[j] = mul2(X[j], Z[j]);
                YZ[j] = mul2(Y[j], Z[j]);
                ACC[j] = 0ull;
            }
        }

        const ulonglong2* recs =
            (const ulonglong2*)(buf ? &sm[1][0] : &sm[0][0]);
#pragma unroll 2
        for (int g = 0; g < GCHUNK; ++g) {
            ulonglong2 q0 = recs[g * 5 + 0];  // Ka00 | Ka11
            ulonglong2 q1 = recs[g * 5 + 1];  // Ka22 | 2Ka01
            ulonglong2 q2 = recs[g * 5 + 2];  // 2Ka02 | 2Ka12
            ulonglong2 q3 = recs[g * 5 + 3];  // bx | by
            ulonglong2 q4 = recs[g * 5 + 4];  // bz | cf

            unsigned long long T[4];
#pragma unroll
            for (int j = 0; j < 4; j++) T[j] = fma2(q0.x, XX[j], q4.y);
#pragma unroll
            for (int j = 0; j < 4; j++) T[j] = fma2(q0.y, YY[j], T[j]);
#pragma unroll
            for (int j = 0; j < 4; j++) T[j] = fma2(q1.x, ZZ[j], T[j]);
#pragma unroll
            for (int j = 0; j < 4; j++) T[j] = fma2(q1.y, XY[j], T[j]);
#pragma unroll
            for (int j = 0; j < 4; j++) T[j] = fma2(q2.x, XZ[j], T[j]);
#pragma unroll
            for (int j = 0; j < 4; j++) T[j] = fma2(q2.y, YZ[j], T[j]);
#pragma unroll
            for (int j = 0; j < 4; j++) T[j] = fma2(q3.x, X[j], T[j]);
#pragma unroll
            for (int j = 0; j < 4; j++) T[j] = fma2(q3.y, Y[j], T[j]);
#pragma unroll
            for (int j = 0; j < 4; j++) T[j] = fma2(q4.x, Z[j], T[j]);

#pragma unroll
            for (int j = 0; j < 4; j++) {
                float f0, f1;
                upk2(T[j], f0, f1);
                float e0 = ex2(f0), e1 = ex2(f1);
                ACC[j] = add2(ACC[j], pk2(e0, e1));
            }
        }
        __syncthreads();
    }

    if (cur_pb >= 0) {
#pragma unroll
        for (int j = 0; j < 4; j++) {
            float a0, a1;
            upk2(ACC[j], a0, a1);
            int p = p0 + j * 512;
            if (p < M)       atomicAdd(out + p, a0);
            if (p + 256 < M) atomicAdd(out + p + 256, a1);
        }
    }
}

// ---------------------------------------------------------------------------
extern "C" void kernel_launch(void* const* d_in, const int* in_sizes, int n_in,
                              void* d_out, int out_size) {
    const float* sample_points = (const float*)d_in[0];
    const float* positions     = (const float*)d_in[1];
    const float* scales        = (const float*)d_in[2];
    const float* rotations     = (const float*)d_in[3];
    const float* intensities   = (const float*)d_in[4];
    float* out = (float*)d_out;

    int M = in_sizes[0] / 3;
    int n = in_sizes[4];
    int n_pad = ((n + GCHUNK - 1) / GCHUNK) * GCHUNK;
    if (n_pad > NG_MAX) n_pad = NG_MAX;

    cudaMemsetAsync(out, 0, (size_t)out_size * sizeof(float));

    prep_kernel<<<(n_pad + 255) / 256, 256>>>(positions, scales, rotations,
                                              intensities, n, n_pad);

    int sms = 148;
    cudaDeviceGetAttribute(&sms, cudaDevAttrMultiProcessorCount, 0);
    int n_ctas = sms * CTAS_PER_SM;

    int pb_tiles = (M + PTS_PER_TILE - 1) / PTS_PER_TILE;   // 32
    int gc_tiles = n_pad / GCHUNK;                           // 64
    int tiles = pb_tiles * gc_tiles;
    if (n_ctas > tiles) n_ctas = tiles;

    gauss_kernel<<<n_ctas, 256>>>(sample_points, out, M, gc_tiles, pb_tiles,
                                  n_ctas);
}